// round 6
// baseline (speedup 1.0000x reference)
#include <cuda_runtime.h>

// ---------------- geometry ----------------
#define RAD    7
#define IMG    2048
#define DOM    2062            // IMG + 2*RAD : iterated domain
#define GUARD  8               // zero guard band around DOM (zero-pad semantics)
#define WB     2176            // buffer width in floats
#define W4     (WB/4)
#define HB     2080            // buffer height
#define PLANE  (HB*WB)
#define NSTRIP 19              // 19 strips * 28 float4 = 532 >= 516 domain float4 cols
#define SROWS  28              // 5 x 74 x 3 = 1110 blocks <= 148 SM x 8 = 1184 (one wave)
#define NRB    74              // ceil(2062/28)
#define NITER  10

// ping-pong state, planar per channel, zero-initialized at module load;
// guard bands are NEVER written -> stay zero across all graph replays
__device__ float g_bufA[3*PLANE];
__device__ float g_bufB[3*PLANE];

// ---------------- pad: img (HWC, edge-pad 7) -> bufA domain region only ----------------
__global__ void pad_kernel(const float* __restrict__ img) {
    int bc = GUARD + blockIdx.x*blockDim.x + threadIdx.x;   // domain col in buffer coords
    int br = GUARD + blockIdx.y;                            // domain row in buffer coords
    int ch = blockIdx.z;
    if (bc >= GUARD+DOM) return;
    int u = br - (GUARD+RAD);
    int w = bc - (GUARD+RAD);
    u = min(max(u,0), IMG-1);
    w = min(max(w,0), IMG-1);
    g_bufA[ch*PLANE + br*WB + bc] = img[(u*IMG + w)*3 + ch];
}

__device__ __forceinline__ float4 f4add(float4 a, float4 b){
    return make_float4(a.x+b.x, a.y+b.y, a.z+b.z, a.w+b.w);
}
__device__ __forceinline__ float4 f4sub(float4 a, float4 b){
    return make_float4(a.x-b.x, a.y-b.y, a.z-b.z, a.w-b.w);
}

// rotate-left-1 key: (abs_bits << 1) | sign  — unsigned order == |value| order,
// bijective with the float bits (recover via rotate-right-1)
__device__ __forceinline__ unsigned keyof(float d) {
    unsigned b = __float_as_uint(d);
    return __funnelshift_l(b, b, 1);
}

// incremental left/right 8-windows from (fine[t-2], ownfine, fine[t+2], chunk sums)
// l[j] = sum w[j+1..j+8], r[j] = sum w[j+8..j+15] with w[k] = value at col 4*(t-2)+k
__device__ __forceinline__ void hwin_cs(float4 fm, float4 own, float4 fp,
                                        float Cm2, float Cm1, float Cown, float Cp1,
                                        float* l, float* r) {
    l[0] = (Cm2 - fm.x) + Cm1 + own.x;
    l[1] = l[0] - fm.y + own.y;
    l[2] = l[1] - fm.z + own.z;
    l[3] = l[2] - fm.w + own.w;
    r[0] = Cown + Cp1;
    r[1] = r[0] - own.x + fp.x;
    r[2] = r[1] - own.y + fp.y;
    r[3] = r[2] - own.z + fp.z;
}

// ---------------- one full side-window iteration, warp-autonomous ----------------
__global__ __launch_bounds__(128,8) void iter_kernel(int sel) {
    __shared__ float4 sF[3][4][32];   // [array: T,B,X][warp][lane] fine float4
    __shared__ float4 sC4[4][32];     // packed chunk sums {cT, cB, cX, 0}

    const int t = threadIdx.x & 31;
    const int w = threadIdx.x >> 5;
    const int strip = blockIdx.x*4 + w;
    if (strip >= NSTRIP) return;      // safe: no __syncthreads in this kernel
    const int ch = blockIdx.z;
    const float* __restrict__ srcp = (sel ? g_bufB : g_bufA) + ch*PLANE;
    float*       __restrict__ dstp = (sel ? g_bufA : g_bufB) + ch*PLANE;
    const float4* __restrict__ src4 = reinterpret_cast<const float4*>(srcp);
    float4*       __restrict__ dst4 = reinterpret_cast<float4*>(dstp);

    const int c4 = strip*28 + t;      // buffer float4 column (max 535 < 544)
    const int r0 = blockIdx.y*SROWS;
    const int rend = min(r0 + SROWS, DOM);

    // warm-up: sT = buffer rows r0+1..r0+8, sB = rows r0+8..r0+15, xc = row r0+8
    float4 sT = make_float4(0,0,0,0), sB = make_float4(0,0,0,0), xc = make_float4(0,0,0,0);
    #pragma unroll
    for (int k = 1; k <= 15; ++k) {
        float4 v = __ldg(&src4[(r0+k)*W4 + c4]);
        if (k <= 8) sT = f4add(sT, v);
        if (k >= 8) sB = f4add(sB, v);
        if (k == 8) xc = v;
    }

    const bool isOut = (t >= 2) && (t < 30) && (c4 <= 517);
    const bool full4 = (c4 <= 516);
    const float S8  = 1.0f/64.0f;
    const float S15 = 1.0f/120.0f;

    for (int i = r0; i < rend; ++i) {
        // prefetch this row's slide inputs early (consumed only at loop bottom)
        float4 aT = __ldg(&src4[(i+9)*W4  + c4]);   // also next row's center
        float4 bT = __ldg(&src4[(i+1)*W4  + c4]);
        float4 aB = __ldg(&src4[(i+16)*W4 + c4]);

        float cT = (sT.x+sT.y)+(sT.z+sT.w);
        float cB = (sB.x+sB.y)+(sB.z+sB.w);
        float cX = (xc.x+xc.y)+(xc.z+xc.w);

        __syncwarp();
        sF[0][w][t] = sT;
        sF[1][w][t] = sB;
        sF[2][w][t] = xc;
        sC4[w][t] = make_float4(cT, cB, cX, 0.f);
        __syncwarp();

        if (isOut) {
            float4 Cm2 = sC4[w][t-2], Cm1 = sC4[w][t-1], Cp1 = sC4[w][t+1];
            float lA[4], rA[4], lB[4], rB[4], lX[4], rX[4];
            {
                float4 fm = sF[0][w][t-2], fp = sF[0][w][t+2];
                hwin_cs(fm, sT, fp, Cm2.x, Cm1.x, cT, Cp1.x, lA, rA);
            }
            {
                float4 fm = sF[1][w][t-2], fp = sF[1][w][t+2];
                hwin_cs(fm, sB, fp, Cm2.y, Cm1.y, cB, Cp1.y, lB, rB);
            }
            {
                float4 fm = sF[2][w][t-2], fp = sF[2][w][t+2];
                hwin_cs(fm, xc, fp, Cm2.z, Cm1.z, cX, Cp1.z, lX, rX);
            }

            const float cAj[4] = { sT.x, sT.y, sT.z, sT.w };
            const float cBj[4] = { sB.x, sB.y, sB.z, sB.w };
            const float xv [4] = { xc.x, xc.y, xc.z, xc.w };
            float res[4];
            #pragma unroll
            for (int j = 0; j < 4; ++j) {
                float fA = lA[j] + rA[j] - cAj[j];      // full-15 horiz of top sums
                float fB = lB[j] + rB[j] - cBj[j];      // full-15 horiz of bottom sums
                float lC = lA[j] + lB[j] - lX[j];       // left-8 of full-15 vertical
                float rC = rA[j] + rB[j] - rX[j];       // right-8 of full-15 vertical
                float x  = xv[j];
                // channel order matches reference stack: NW NE SW SE N S W E
                float d0 = fmaf(lA[j], S8,  -x);
                float d1 = fmaf(rA[j], S8,  -x);
                float d2 = fmaf(lB[j], S8,  -x);
                float d3 = fmaf(rB[j], S8,  -x);
                float d4 = fmaf(fA,    S15, -x);
                float d5 = fmaf(fB,    S15, -x);
                float d6 = fmaf(lC,    S15, -x);
                float d7 = fmaf(rC,    S15, -x);
                // min-|d| via rotated-bits unsigned keys, depth-3 IMNMX tree
                unsigned k0 = keyof(d0), k1 = keyof(d1), k2 = keyof(d2), k3 = keyof(d3);
                unsigned k4 = keyof(d4), k5 = keyof(d5), k6 = keyof(d6), k7 = keyof(d7);
                unsigned m = min(min(min(k0,k1), min(k2,k3)),
                                 min(min(k4,k5), min(k6,k7)));
                float best = __uint_as_float(__funnelshift_r(m, m, 1));
                res[j] = x + best;
            }
            if (full4) {
                dst4[(i+8)*W4 + c4] = make_float4(res[0], res[1], res[2], res[3]);
            } else {
                // c4 == 517: only buffer cols 2068, 2069 are inside the domain
                dstp[(i+8)*WB + 4*c4 + 0] = res[0];
                dstp[(i+8)*WB + 4*c4 + 1] = res[1];
            }
        }

        // slide vertical windows to row i+1; reuse aT as next center row
        sT = f4sub(f4add(sT, aT), bT);
        sB = f4sub(f4add(sB, aB), xc);
        xc = aT;
    }
}

// ---------------- crop: bufA planar -> d_out HWC ----------------
__global__ void crop_kernel(float* __restrict__ out) {
    int x = blockIdx.x*blockDim.x + threadIdx.x;
    int y = blockIdx.y;
    if (x >= IMG) return;
    int br = y + RAD + GUARD;
    int bc = x + RAD + GUARD;
    float* o = out + (size_t)(y*IMG + x)*3;
    o[0] = g_bufA[0*PLANE + br*WB + bc];
    o[1] = g_bufA[1*PLANE + br*WB + bc];
    o[2] = g_bufA[2*PLANE + br*WB + bc];
}

extern "C" void kernel_launch(void* const* d_in, const int* in_sizes, int n_in,
                              void* d_out, int out_size) {
    (void)in_sizes; (void)n_in; (void)out_size;
    const float* img = (const float*)d_in[0];   // d_in[1], d_in[2] are fixed constant kernels
    float* out = (float*)d_out;

    pad_kernel<<<dim3((DOM + 255)/256, DOM, 3), 256>>>(img);

    for (int it = 0; it < NITER; ++it)
        iter_kernel<<<dim3(5, NRB, 3), 128>>>(it & 1);
    // it=0: A->B, it=1: B->A, ... it=9: B->A  => final state in g_bufA

    crop_kernel<<<dim3((IMG + 255)/256, IMG), 256>>>(out);
}

// round 7
// speedup vs baseline: 1.0817x; 1.0817x over previous
#include <cuda_runtime.h>

// ---------------- geometry ----------------
#define RAD    7
#define IMG    2048
#define DOM    2062            // IMG + 2*RAD : iterated domain
#define GUARD  8               // zero guard band around DOM (zero-pad semantics)
#define WB     2176            // buffer width in floats
#define W4     (WB/4)
#define HB     2080            // buffer height
#define PLANE  (HB*WB)
#define NSTRIP 19              // 19 strips * 28 float4 = 532 >= 516 domain float4 cols
#define SROWS  35              // 5 x 59 x 3 = 885 blocks <= 148 SM x 6 = 888 (one wave)
#define NRB    59              // 59*35 = 2065 >= 2062
#define NITER  10

// ping-pong state, planar per channel, zero-initialized at module load;
// guard bands are NEVER written -> stay zero across all graph replays
__device__ float g_bufA[3*PLANE];
__device__ float g_bufB[3*PLANE];

// ---------------- pad: img (HWC, edge-pad 7) -> bufA domain region only ----------------
__global__ void pad_kernel(const float* __restrict__ img) {
    int bc = GUARD + blockIdx.x*blockDim.x + threadIdx.x;   // domain col in buffer coords
    int br = GUARD + blockIdx.y;                            // domain row in buffer coords
    int ch = blockIdx.z;
    if (bc >= GUARD+DOM) return;
    int u = br - (GUARD+RAD);
    int w = bc - (GUARD+RAD);
    u = min(max(u,0), IMG-1);
    w = min(max(w,0), IMG-1);
    g_bufA[ch*PLANE + br*WB + bc] = img[(u*IMG + w)*3 + ch];
}

__device__ __forceinline__ float4 f4add(float4 a, float4 b){
    return make_float4(a.x+b.x, a.y+b.y, a.z+b.z, a.w+b.w);
}
__device__ __forceinline__ float4 f4sub(float4 a, float4 b){
    return make_float4(a.x-b.x, a.y-b.y, a.z-b.z, a.w-b.w);
}

// rotate-left-1 key: (abs_bits << 1) | sign  — unsigned order == |value| order,
// bijective with the float bits (recover via rotate-right-1)
__device__ __forceinline__ unsigned keyof(float d) {
    unsigned b = __float_as_uint(d);
    return __funnelshift_l(b, b, 1);
}

// 8-wide left/right window sums for this lane's 4 columns, all-shuffle exchange.
// Lane t owns chunk cols [4t, 4t+4). With w[k] = value at col 4(t-2)+k:
//   l[j] = sum w[j+1 .. j+8], r[j] = sum w[j+8 .. j+15]
__device__ __forceinline__ void awin(float4 a, float* l, float* r) {
    const unsigned FULL = 0xffffffffu;
    float P2 = a.x + a.y;
    float P3 = P2 + a.z;
    float S2 = a.z + a.w;
    float S3 = a.y + S2;
    float C  = P3 + a.w;
    float uS1 = __shfl_up_sync  (FULL, a.w, 2);
    float uS2 = __shfl_up_sync  (FULL, S2,  2);
    float uS3 = __shfl_up_sync  (FULL, S3,  2);
    float uC  = __shfl_up_sync  (FULL, C,   1);
    float dC  = __shfl_down_sync(FULL, C,   1);
    float dP1 = __shfl_down_sync(FULL, a.x, 2);
    float dP2 = __shfl_down_sync(FULL, P2,  2);
    float dP3 = __shfl_down_sync(FULL, P3,  2);
    l[0] = uS3 + uC + a.x;
    l[1] = uS2 + uC + P2;
    l[2] = uS1 + uC + P3;
    l[3] = uC  + C;
    r[0] = C   + dC;
    r[1] = S3  + dC + dP1;
    r[2] = S2  + dC + dP2;
    r[3] = a.w + dC + dP3;
}

// ---------------- one full side-window iteration, shuffle-only exchange ----------------
__global__ __launch_bounds__(128,6) void iter_kernel(int sel) {
    const int t = threadIdx.x & 31;
    const int w = threadIdx.x >> 5;
    const int strip = blockIdx.x*4 + w;
    if (strip >= NSTRIP) return;      // warps fully independent, no block sync anywhere
    const int ch = blockIdx.z;
    const float* __restrict__ srcp = (sel ? g_bufB : g_bufA) + ch*PLANE;
    float*       __restrict__ dstp = (sel ? g_bufA : g_bufB) + ch*PLANE;
    const float4* __restrict__ src4 = reinterpret_cast<const float4*>(srcp);
    float4*       __restrict__ dst4 = reinterpret_cast<float4*>(dstp);

    const int c4 = strip*28 + t;      // buffer float4 column (max 535 < 544)
    const int r0 = blockIdx.y*SROWS;
    const int rend = min(r0 + SROWS, DOM);

    // warm-up: sT = buffer rows r0+1..r0+8, sB = rows r0+8..r0+15, xc = row r0+8
    float4 sT = make_float4(0,0,0,0), sB = make_float4(0,0,0,0), xc = make_float4(0,0,0,0);
    #pragma unroll
    for (int k = 1; k <= 15; ++k) {
        float4 v = __ldg(&src4[(r0+k)*W4 + c4]);
        if (k <= 8) sT = f4add(sT, v);
        if (k >= 8) sB = f4add(sB, v);
        if (k == 8) xc = v;
    }

    const bool isOut = (t >= 2) && (t < 30) && (c4 <= 517);
    const bool full4 = (c4 <= 516);
    const float S8  = 1.0f/64.0f;
    const float S15 = 1.0f/120.0f;

    for (int i = r0; i < rend; ++i) {
        // prefetch this row's slide inputs early (consumed only at loop bottom)
        float4 aT = __ldg(&src4[(i+9)*W4  + c4]);   // also next row's center
        float4 bT = __ldg(&src4[(i+1)*W4  + c4]);
        float4 aB = __ldg(&src4[(i+16)*W4 + c4]);

        // full 15-row vertical sum
        float4 sV = f4sub(f4add(sT, sB), xc);

        // horizontal windows via warp shuffles (all lanes participate)
        float lT[4], rT[4], lB[4], rB[4], lV[4], rV[4];
        awin(sT, lT, rT);
        awin(sB, lB, rB);
        awin(sV, lV, rV);

        if (isOut) {
            const float fT[4] = { sT.x, sT.y, sT.z, sT.w };
            const float fB[4] = { sB.x, sB.y, sB.z, sB.w };
            const float xv[4] = { xc.x, xc.y, xc.z, xc.w };
            float res[4];
            #pragma unroll
            for (int j = 0; j < 4; ++j) {
                float x  = xv[j];
                float fA = lT[j] + rT[j] - fT[j];    // full-15 horiz of top sums (N)
                float fS = lB[j] + rB[j] - fB[j];    // full-15 horiz of bottom sums (S)
                // channel order matches reference stack: NW NE SW SE N S W E
                float d0 = fmaf(lT[j], S8,  -x);
                float d1 = fmaf(rT[j], S8,  -x);
                float d2 = fmaf(lB[j], S8,  -x);
                float d3 = fmaf(rB[j], S8,  -x);
                float d4 = fmaf(fA,    S15, -x);
                float d5 = fmaf(fS,    S15, -x);
                float d6 = fmaf(lV[j], S15, -x);
                float d7 = fmaf(rV[j], S15, -x);
                // min-|d| via rotated-bits unsigned keys, depth-3 IMNMX tree
                unsigned k0 = keyof(d0), k1 = keyof(d1), k2 = keyof(d2), k3 = keyof(d3);
                unsigned k4 = keyof(d4), k5 = keyof(d5), k6 = keyof(d6), k7 = keyof(d7);
                unsigned m = min(min(min(k0,k1), min(k2,k3)),
                                 min(min(k4,k5), min(k6,k7)));
                float best = __uint_as_float(__funnelshift_r(m, m, 1));
                res[j] = x + best;
            }
            if (full4) {
                dst4[(i+8)*W4 + c4] = make_float4(res[0], res[1], res[2], res[3]);
            } else {
                // c4 == 517: only buffer cols 2068, 2069 are inside the domain
                dstp[(i+8)*WB + 4*c4 + 0] = res[0];
                dstp[(i+8)*WB + 4*c4 + 1] = res[1];
            }
        }

        // slide vertical windows to row i+1; reuse aT as next center row
        sT = f4sub(f4add(sT, aT), bT);
        sB = f4sub(f4add(sB, aB), xc);
        xc = aT;
    }
}

// ---------------- crop: bufA planar -> d_out HWC ----------------
__global__ void crop_kernel(float* __restrict__ out) {
    int x = blockIdx.x*blockDim.x + threadIdx.x;
    int y = blockIdx.y;
    if (x >= IMG) return;
    int br = y + RAD + GUARD;
    int bc = x + RAD + GUARD;
    float* o = out + (size_t)(y*IMG + x)*3;
    o[0] = g_bufA[0*PLANE + br*WB + bc];
    o[1] = g_bufA[1*PLANE + br*WB + bc];
    o[2] = g_bufA[2*PLANE + br*WB + bc];
}

extern "C" void kernel_launch(void* const* d_in, const int* in_sizes, int n_in,
                              void* d_out, int out_size) {
    (void)in_sizes; (void)n_in; (void)out_size;
    const float* img = (const float*)d_in[0];   // d_in[1], d_in[2] are fixed constant kernels
    float* out = (float*)d_out;

    pad_kernel<<<dim3((DOM + 255)/256, DOM, 3), 256>>>(img);

    for (int it = 0; it < NITER; ++it)
        iter_kernel<<<dim3(5, NRB, 3), 128>>>(it & 1);
    // it=0: A->B, it=1: B->A, ... it=9: B->A  => final state in g_bufA

    crop_kernel<<<dim3((IMG + 255)/256, IMG), 256>>>(out);
}

// round 8
// speedup vs baseline: 1.1101x; 1.0263x over previous
#include <cuda_runtime.h>

// ---------------- geometry ----------------
#define RAD    7
#define IMG    2048
#define DOM    2062            // IMG + 2*RAD : iterated domain
#define GUARD  8               // zero guard band around DOM (zero-pad semantics)
#define WB     2176            // buffer width in floats
#define W4     (WB/4)
#define HB     2080            // buffer height
#define PLANE  (HB*WB)
#define NSTRIP 19              // 19 strips * 28 float4 = 532 >= 516 domain float4 cols
#define SROWS  42              // even; 5 x 50 x 3 = 750 blocks ~ 148 SM x 5 = 740 slots
#define NRB    50              // 50*42 = 2100 >= 2062; last block gets 4 rows (even)
#define NITER  10

// ping-pong state, planar per channel, zero-initialized at module load;
// guard bands are NEVER written -> stay zero across all graph replays
__device__ float g_bufA[3*PLANE];
__device__ float g_bufB[3*PLANE];

// ---------------- pad: img (HWC, edge-pad 7) -> bufA domain region only ----------------
__global__ void pad_kernel(const float* __restrict__ img) {
    int bc = GUARD + blockIdx.x*blockDim.x + threadIdx.x;   // domain col in buffer coords
    int br = GUARD + blockIdx.y;                            // domain row in buffer coords
    int ch = blockIdx.z;
    if (bc >= GUARD+DOM) return;
    int u = br - (GUARD+RAD);
    int w = bc - (GUARD+RAD);
    u = min(max(u,0), IMG-1);
    w = min(max(w,0), IMG-1);
    g_bufA[ch*PLANE + br*WB + bc] = img[(u*IMG + w)*3 + ch];
}

__device__ __forceinline__ float4 f4add(float4 a, float4 b){
    return make_float4(a.x+b.x, a.y+b.y, a.z+b.z, a.w+b.w);
}
__device__ __forceinline__ float4 f4sub(float4 a, float4 b){
    return make_float4(a.x-b.x, a.y-b.y, a.z-b.z, a.w-b.w);
}

// rotate-left-1 key: (abs_bits << 1) | sign  — unsigned order == |value| order,
// bijective with the float bits (recover via rotate-right-1)
__device__ __forceinline__ unsigned keyof(float d) {
    unsigned b = __float_as_uint(d);
    return __funnelshift_l(b, b, 1);
}

// 8-wide left/right window sums for this lane's 4 columns, all-shuffle exchange.
// Lane t owns chunk cols [4t, 4t+4). With w[k] = value at col 4(t-2)+k:
//   l[j] = sum w[j+1 .. j+8], r[j] = sum w[j+8 .. j+15]
__device__ __forceinline__ void awin(float4 a, float* l, float* r) {
    const unsigned FULL = 0xffffffffu;
    float P2 = a.x + a.y;
    float P3 = P2 + a.z;
    float S2 = a.z + a.w;
    float S3 = a.y + S2;
    float C  = P3 + a.w;
    float uS1 = __shfl_up_sync  (FULL, a.w, 2);
    float uS2 = __shfl_up_sync  (FULL, S2,  2);
    float uS3 = __shfl_up_sync  (FULL, S3,  2);
    float uC  = __shfl_up_sync  (FULL, C,   1);
    float dC  = __shfl_down_sync(FULL, C,   1);
    float dP1 = __shfl_down_sync(FULL, a.x, 2);
    float dP2 = __shfl_down_sync(FULL, P2,  2);
    float dP3 = __shfl_down_sync(FULL, P3,  2);
    l[0] = uS3 + uC + a.x;
    l[1] = uS2 + uC + P2;
    l[2] = uS1 + uC + P3;
    l[3] = uC  + C;
    r[0] = C   + dC;
    r[1] = S3  + dC + dP1;
    r[2] = S2  + dC + dP2;
    r[3] = a.w + dC + dP3;
}

// full side-window pass for one row; unconditional compute, predicated store
__device__ __forceinline__ void do_row(float4 sT, float4 sB, float4 xc, int i,
                                       float4* __restrict__ dst4,
                                       float*  __restrict__ dstp,
                                       int c4, bool isOut, bool full4) {
    const float S8  = 1.0f/64.0f;
    const float S15 = 1.0f/120.0f;

    float4 sV = f4sub(f4add(sT, sB), xc);     // full 15-row vertical sum

    float lT[4], rT[4], lB[4], rB[4], lV[4], rV[4];
    awin(sT, lT, rT);
    awin(sB, lB, rB);
    awin(sV, lV, rV);

    const float fT[4] = { sT.x, sT.y, sT.z, sT.w };
    const float fB[4] = { sB.x, sB.y, sB.z, sB.w };
    const float xv[4] = { xc.x, xc.y, xc.z, xc.w };
    float res[4];
    #pragma unroll
    for (int j = 0; j < 4; ++j) {
        float x  = xv[j];
        float fA = lT[j] + rT[j] - fT[j];      // full-15 horiz of top sums (N)
        float fS = lB[j] + rB[j] - fB[j];      // full-15 horiz of bottom sums (S)
        // channel order matches reference stack: NW NE SW SE N S W E
        float d0 = fmaf(lT[j], S8,  -x);
        float d1 = fmaf(rT[j], S8,  -x);
        float d2 = fmaf(lB[j], S8,  -x);
        float d3 = fmaf(rB[j], S8,  -x);
        float d4 = fmaf(fA,    S15, -x);
        float d5 = fmaf(fS,    S15, -x);
        float d6 = fmaf(lV[j], S15, -x);
        float d7 = fmaf(rV[j], S15, -x);
        // min-|d| via rotated-bits unsigned keys, depth-3 IMNMX tree
        unsigned k0 = keyof(d0), k1 = keyof(d1), k2 = keyof(d2), k3 = keyof(d3);
        unsigned k4 = keyof(d4), k5 = keyof(d5), k6 = keyof(d6), k7 = keyof(d7);
        unsigned m = min(min(min(k0,k1), min(k2,k3)),
                         min(min(k4,k5), min(k6,k7)));
        float best = __uint_as_float(__funnelshift_r(m, m, 1));
        res[j] = x + best;
    }
    if (isOut & full4) {
        dst4[(i+8)*W4 + c4] = make_float4(res[0], res[1], res[2], res[3]);
    } else if (isOut) {
        // c4 == 517: only buffer cols 2068, 2069 are inside the domain
        dstp[(i+8)*WB + 4*c4 + 0] = res[0];
        dstp[(i+8)*WB + 4*c4 + 1] = res[1];
    }
}

// ---------------- one full side-window iteration, 2 rows per loop ----------------
__global__ __launch_bounds__(128,5) void iter_kernel(int sel) {
    const int t = threadIdx.x & 31;
    const int w = threadIdx.x >> 5;
    const int strip = blockIdx.x*4 + w;
    if (strip >= NSTRIP) return;      // warps fully independent, no block sync anywhere
    const int ch = blockIdx.z;
    const float* __restrict__ srcp = (sel ? g_bufB : g_bufA) + ch*PLANE;
    float*       __restrict__ dstp = (sel ? g_bufA : g_bufB) + ch*PLANE;
    const float4* __restrict__ src4 = reinterpret_cast<const float4*>(srcp);
    float4*       __restrict__ dst4 = reinterpret_cast<float4*>(dstp);

    const int c4 = strip*28 + t;      // buffer float4 column (max 535 < 544)
    const int r0 = blockIdx.y*SROWS;
    const int rend = min(r0 + SROWS, DOM);   // rend - r0 is always even (42 or 4)

    // warm-up: sT = buffer rows r0+1..r0+8, sB = rows r0+8..r0+15, xc = row r0+8
    float4 sT = make_float4(0,0,0,0), sB = make_float4(0,0,0,0), xc = make_float4(0,0,0,0);
    #pragma unroll
    for (int k = 1; k <= 15; ++k) {
        float4 v = __ldg(&src4[(r0+k)*W4 + c4]);
        if (k <= 8) sT = f4add(sT, v);
        if (k >= 8) sB = f4add(sB, v);
        if (k == 8) xc = v;
    }

    const bool isOut = (t >= 2) && (t < 30) && (c4 <= 517);
    const bool full4 = (c4 <= 516);

    for (int i = r0; i < rend; i += 2) {
        // all six slide inputs for the row pair, issued up front
        float4 rA = __ldg(&src4[(i+9)*W4  + c4]);   // aT for row i; center of row i+1
        float4 rB = __ldg(&src4[(i+1)*W4  + c4]);   // bT for row i
        float4 rC = __ldg(&src4[(i+16)*W4 + c4]);   // aB for row i
        float4 rD = __ldg(&src4[(i+10)*W4 + c4]);   // aT for row i+1; next center
        float4 rE = __ldg(&src4[(i+2)*W4  + c4]);   // bT for row i+1
        float4 rF = __ldg(&src4[(i+17)*W4 + c4]);   // aB for row i+1

        do_row(sT, sB, xc, i, dst4, dstp, c4, isOut, full4);

        float4 sT1 = f4sub(f4add(sT, rA), rB);
        float4 sB1 = f4sub(f4add(sB, rC), xc);

        do_row(sT1, sB1, rA, i+1, dst4, dstp, c4, isOut, full4);

        sT = f4sub(f4add(sT1, rD), rE);
        sB = f4sub(f4add(sB1, rF), rA);
        xc = rD;
    }
}

// ---------------- crop: bufA planar -> d_out HWC ----------------
__global__ void crop_kernel(float* __restrict__ out) {
    int x = blockIdx.x*blockDim.x + threadIdx.x;
    int y = blockIdx.y;
    if (x >= IMG) return;
    int br = y + RAD + GUARD;
    int bc = x + RAD + GUARD;
    float* o = out + (size_t)(y*IMG + x)*3;
    o[0] = g_bufA[0*PLANE + br*WB + bc];
    o[1] = g_bufA[1*PLANE + br*WB + bc];
    o[2] = g_bufA[2*PLANE + br*WB + bc];
}

extern "C" void kernel_launch(void* const* d_in, const int* in_sizes, int n_in,
                              void* d_out, int out_size) {
    (void)in_sizes; (void)n_in; (void)out_size;
    const float* img = (const float*)d_in[0];   // d_in[1], d_in[2] are fixed constant kernels
    float* out = (float*)d_out;

    pad_kernel<<<dim3((DOM + 255)/256, DOM, 3), 256>>>(img);

    for (int it = 0; it < NITER; ++it)
        iter_kernel<<<dim3(5, NRB, 3), 128>>>(it & 1);
    // it=0: A->B, it=1: B->A, ... it=9: B->A  => final state in g_bufA

    crop_kernel<<<dim3((IMG + 255)/256, IMG), 256>>>(out);
}

// round 9
// speedup vs baseline: 1.1160x; 1.0053x over previous
#include <cuda_runtime.h>

// ---------------- geometry ----------------
#define RAD    7
#define IMG    2048
#define DOM    2062            // IMG + 2*RAD : iterated domain
#define GUARD  8               // zero guard band around DOM (zero-pad semantics)
#define WB     2176            // buffer width in floats
#define W4     (WB/4)
#define HB     2080            // buffer height
#define PLANE  (HB*WB)
#define NSTRIP 19              // 19 strips * 28 float4 = 532 >= 516 domain float4 cols
#define SROWS  44              // even; 5 x 47 x 3 = 705 blocks <= 148 SM x 5 = 740 (one wave)
#define NRB    47              // 46*44 = 2024; last block rows 2024..2061 = 38 (even)
#define NITER  10

// ping-pong state, planar per channel, zero-initialized at module load;
// guard bands are NEVER written -> stay zero across all graph replays
__device__ float g_bufA[3*PLANE];
__device__ float g_bufB[3*PLANE];

// ---------------- pad: img (HWC, edge-pad 7) -> bufA domain region only ----------------
__global__ void pad_kernel(const float* __restrict__ img) {
    int bc = GUARD + blockIdx.x*blockDim.x + threadIdx.x;   // domain col in buffer coords
    int br = GUARD + blockIdx.y;                            // domain row in buffer coords
    int ch = blockIdx.z;
    if (bc >= GUARD+DOM) return;
    int u = br - (GUARD+RAD);
    int w = bc - (GUARD+RAD);
    u = min(max(u,0), IMG-1);
    w = min(max(w,0), IMG-1);
    g_bufA[ch*PLANE + br*WB + bc] = img[(u*IMG + w)*3 + ch];
}

// ---------------- packed f32x2 helpers (Blackwell) ----------------
typedef unsigned long long u64;
#define NEG1P 0xBF800000BF800000ULL     // {-1.0f, -1.0f}

__device__ __forceinline__ u64 pk2(float lo, float hi){
    u64 r; asm("mov.b64 %0, {%1, %2};" : "=l"(r) : "f"(lo), "f"(hi)); return r;
}
__device__ __forceinline__ void up2(u64 v, float& lo, float& hi){
    asm("mov.b64 {%0, %1}, %2;" : "=f"(lo), "=f"(hi) : "l"(v));
}
__device__ __forceinline__ u64 fadd2(u64 a, u64 b){
    u64 r; asm("add.rn.f32x2 %0, %1, %2;" : "=l"(r) : "l"(a), "l"(b)); return r;
}
__device__ __forceinline__ u64 fmul2(u64 a, u64 b){
    u64 r; asm("mul.rn.f32x2 %0, %1, %2;" : "=l"(r) : "l"(a), "l"(b)); return r;
}
__device__ __forceinline__ u64 ffma2(u64 a, u64 b, u64 c){
    u64 r; asm("fma.rn.f32x2 %0, %1, %2, %3;" : "=l"(r) : "l"(a), "l"(b), "l"(c)); return r;
}
__device__ __forceinline__ u64 fsub2(u64 a, u64 b){     // a - b (exact: fma(b,-1,a))
    return ffma2(b, NEG1P, a);
}

struct P4 { u64 ab, cd; };               // packed float4: {x,y},{z,w}
__device__ __forceinline__ P4 p4add(P4 a, P4 b){ P4 r; r.ab=fadd2(a.ab,b.ab); r.cd=fadd2(a.cd,b.cd); return r; }
__device__ __forceinline__ P4 p4sub(P4 a, P4 b){ P4 r; r.ab=fsub2(a.ab,b.ab); r.cd=fsub2(a.cd,b.cd); return r; }
__device__ __forceinline__ P4 ldp4(const float4* p){
    float4 v = __ldg(p);
    P4 r; r.ab = pk2(v.x, v.y); r.cd = pk2(v.z, v.w); return r;
}

// rotate-left-1 key: (abs_bits << 1) | sign  — unsigned order == |value| order,
// bijective with the float bits (recover via rotate-right-1)
__device__ __forceinline__ unsigned keyof(float d) {
    unsigned b = __float_as_uint(d);
    return __funnelshift_l(b, b, 1);
}

// 8-wide left/right window sums for this lane's 4 columns, all-shuffle exchange.
// Lane t owns chunk cols [4t, 4t+4). With w[k] = value at col 4(t-2)+k:
//   l[j] = sum w[j+1 .. j+8], r[j] = sum w[j+8 .. j+15]
__device__ __forceinline__ void awin(float ax, float ay, float az, float aw,
                                     float* l, float* r) {
    const unsigned FULL = 0xffffffffu;
    float P2 = ax + ay;
    float P3 = P2 + az;
    float S2 = az + aw;
    float S3 = ay + S2;
    float C  = P3 + aw;
    float uS1 = __shfl_up_sync  (FULL, aw, 2);
    float uS2 = __shfl_up_sync  (FULL, S2, 2);
    float uS3 = __shfl_up_sync  (FULL, S3, 2);
    float uC  = __shfl_up_sync  (FULL, C,  1);
    float dC  = __shfl_down_sync(FULL, C,  1);
    float dP1 = __shfl_down_sync(FULL, ax, 2);
    float dP2 = __shfl_down_sync(FULL, P2, 2);
    float dP3 = __shfl_down_sync(FULL, P3, 2);
    l[0] = uS3 + uC + ax;
    l[1] = uS2 + uC + P2;
    l[2] = uS1 + uC + P3;
    l[3] = uC  + C;
    r[0] = C   + dC;
    r[1] = S3  + dC + dP1;
    r[2] = S2  + dC + dP2;
    r[3] = aw  + dC + dP3;
}

// full side-window pass for one row; unconditional compute, predicated store
__device__ __forceinline__ void do_row(P4 sT, P4 sB, P4 xc, int i,
                                       float4* __restrict__ dst4,
                                       float*  __restrict__ dstp,
                                       int c4, bool isOut, bool full4) {
    const u64 S8p  = pk2(1.0f/64.0f,  1.0f/64.0f);
    const u64 S15p = pk2(1.0f/120.0f, 1.0f/120.0f);

    // full 15-row vertical sum (packed)
    u64 sVab = fsub2(fadd2(sT.ab, sB.ab), xc.ab);
    u64 sVcd = fsub2(fadd2(sT.cd, sB.cd), xc.cd);

    float t0,t1,t2,t3, b0,b1,b2,b3, v0,v1,v2,v3;
    up2(sT.ab, t0,t1); up2(sT.cd, t2,t3);
    up2(sB.ab, b0,b1); up2(sB.cd, b2,b3);
    up2(sVab,  v0,v1); up2(sVcd,  v2,v3);

    float lT[4], rT[4], lB[4], rB[4], lV[4], rV[4];
    awin(t0,t1,t2,t3, lT, rT);
    awin(b0,b1,b2,b3, lB, rB);
    awin(v0,v1,v2,v3, lV, rV);

    float res[4];
    #pragma unroll
    for (int p = 0; p < 2; ++p) {       // pixel pairs (j0,j1) and (j2,j3)
        u64 xp  = p ? xc.cd : xc.ab;
        u64 fTp = p ? sT.cd : sT.ab;
        u64 fBp = p ? sB.cd : sB.ab;
        u64 lTp = pk2(lT[2*p], lT[2*p+1]);
        u64 rTp = pk2(rT[2*p], rT[2*p+1]);
        u64 lBp = pk2(lB[2*p], lB[2*p+1]);
        u64 rBp = pk2(rB[2*p], rB[2*p+1]);
        u64 lVp = pk2(lV[2*p], lV[2*p+1]);
        u64 rVp = pk2(rV[2*p], rV[2*p+1]);

        u64 nx  = fmul2(xp, NEG1P);                 // exact -x pair
        u64 fAp = fsub2(fadd2(lTp, rTp), fTp);      // full-15 horiz of top sums (N)
        u64 fSp = fsub2(fadd2(lBp, rBp), fBp);      // full-15 horiz of bottom sums (S)

        // channel order matches reference stack: NW NE SW SE N S W E
        u64 d0 = ffma2(lTp, S8p,  nx);
        u64 d1 = ffma2(rTp, S8p,  nx);
        u64 d2 = ffma2(lBp, S8p,  nx);
        u64 d3 = ffma2(rBp, S8p,  nx);
        u64 d4 = ffma2(fAp, S15p, nx);
        u64 d5 = ffma2(fSp, S15p, nx);
        u64 d6 = ffma2(lVp, S15p, nx);
        u64 d7 = ffma2(rVp, S15p, nx);

        float e0,f0_, e1,f1_, e2,f2_, e3,f3_, e4,f4_, e5,f5_, e6,f6_, e7,f7_;
        up2(d0, e0,f0_); up2(d1, e1,f1_); up2(d2, e2,f2_); up2(d3, e3,f3_);
        up2(d4, e4,f4_); up2(d5, e5,f5_); up2(d6, e6,f6_); up2(d7, e7,f7_);
        float xlo, xhi; up2(xp, xlo, xhi);

        {   // element 2p : min-|d| via rotated-bits unsigned keys, depth-3 IMNMX tree
            unsigned m = min(min(min(keyof(e0),keyof(e1)), min(keyof(e2),keyof(e3))),
                             min(min(keyof(e4),keyof(e5)), min(keyof(e6),keyof(e7))));
            res[2*p] = xlo + __uint_as_float(__funnelshift_r(m, m, 1));
        }
        {   // element 2p+1
            unsigned m = min(min(min(keyof(f0_),keyof(f1_)), min(keyof(f2_),keyof(f3_))),
                             min(min(keyof(f4_),keyof(f5_)), min(keyof(f6_),keyof(f7_))));
            res[2*p+1] = xhi + __uint_as_float(__funnelshift_r(m, m, 1));
        }
    }

    if (isOut & full4) {
        dst4[(i+8)*W4 + c4] = make_float4(res[0], res[1], res[2], res[3]);
    } else if (isOut) {
        // c4 == 517: only buffer cols 2068, 2069 are inside the domain
        dstp[(i+8)*WB + 4*c4 + 0] = res[0];
        dstp[(i+8)*WB + 4*c4 + 1] = res[1];
    }
}

// ---------------- one full side-window iteration, 2 rows per loop ----------------
__global__ __launch_bounds__(128,5) void iter_kernel(int sel) {
    const int t = threadIdx.x & 31;
    const int w = threadIdx.x >> 5;
    const int strip = blockIdx.x*4 + w;
    if (strip >= NSTRIP) return;      // warps fully independent, no block sync anywhere
    const int ch = blockIdx.z;
    const float* __restrict__ srcp = (sel ? g_bufB : g_bufA) + ch*PLANE;
    float*       __restrict__ dstp = (sel ? g_bufA : g_bufB) + ch*PLANE;
    const float4* __restrict__ src4 = reinterpret_cast<const float4*>(srcp);
    float4*       __restrict__ dst4 = reinterpret_cast<float4*>(dstp);

    const int c4 = strip*28 + t;      // buffer float4 column (max 535 < 544)
    const int r0 = blockIdx.y*SROWS;
    const int rend = min(r0 + SROWS, DOM);   // rend - r0 always even (44 or 38)

    // warm-up: sT = buffer rows r0+1..r0+8, sB = rows r0+8..r0+15, xc = row r0+8
    P4 sT; sT.ab = 0; sT.cd = 0;
    P4 sB; sB.ab = 0; sB.cd = 0;
    P4 xc; xc.ab = 0; xc.cd = 0;
    #pragma unroll
    for (int k = 1; k <= 15; ++k) {
        P4 v = ldp4(&src4[(r0+k)*W4 + c4]);
        if (k <= 8) sT = p4add(sT, v);
        if (k >= 8) sB = p4add(sB, v);
        if (k == 8) xc = v;
    }

    const bool isOut = (t >= 2) && (t < 30) && (c4 <= 517);
    const bool full4 = (c4 <= 516);

    for (int i = r0; i < rend; i += 2) {
        // all six slide inputs for the row pair, issued up front
        P4 rA = ldp4(&src4[(i+9)*W4  + c4]);   // aT for row i; center of row i+1
        P4 rB = ldp4(&src4[(i+1)*W4  + c4]);   // bT for row i
        P4 rC = ldp4(&src4[(i+16)*W4 + c4]);   // aB for row i
        P4 rD = ldp4(&src4[(i+10)*W4 + c4]);   // aT for row i+1; next center
        P4 rE = ldp4(&src4[(i+2)*W4  + c4]);   // bT for row i+1
        P4 rF = ldp4(&src4[(i+17)*W4 + c4]);   // aB for row i+1

        do_row(sT, sB, xc, i, dst4, dstp, c4, isOut, full4);

        P4 sT1 = p4sub(p4add(sT, rA), rB);
        P4 sB1 = p4sub(p4add(sB, rC), xc);

        do_row(sT1, sB1, rA, i+1, dst4, dstp, c4, isOut, full4);

        sT = p4sub(p4add(sT1, rD), rE);
        sB = p4sub(p4add(sB1, rF), rA);
        xc = rD;
    }
}

// ---------------- crop: bufA planar -> d_out HWC ----------------
__global__ void crop_kernel(float* __restrict__ out) {
    int x = blockIdx.x*blockDim.x + threadIdx.x;
    int y = blockIdx.y;
    if (x >= IMG) return;
    int br = y + RAD + GUARD;
    int bc = x + RAD + GUARD;
    float* o = out + (size_t)(y*IMG + x)*3;
    o[0] = g_bufA[0*PLANE + br*WB + bc];
    o[1] = g_bufA[1*PLANE + br*WB + bc];
    o[2] = g_bufA[2*PLANE + br*WB + bc];
}

extern "C" void kernel_launch(void* const* d_in, const int* in_sizes, int n_in,
                              void* d_out, int out_size) {
    (void)in_sizes; (void)n_in; (void)out_size;
    const float* img = (const float*)d_in[0];   // d_in[1], d_in[2] are fixed constant kernels
    float* out = (float*)d_out;

    pad_kernel<<<dim3((DOM + 255)/256, DOM, 3), 256>>>(img);

    for (int it = 0; it < NITER; ++it)
        iter_kernel<<<dim3(5, NRB, 3), 128>>>(it & 1);
    // it=0: A->B, it=1: B->A, ... it=9: B->A  => final state in g_bufA

    crop_kernel<<<dim3((IMG + 255)/256, IMG), 256>>>(out);
}

// round 10
// speedup vs baseline: 1.1765x; 1.0542x over previous
#include <cuda_runtime.h>

// ---------------- geometry ----------------
#define RAD    7
#define IMG    2048
#define DOM    2062            // IMG + 2*RAD : iterated domain
#define GUARD  8               // zero guard band around DOM (zero-pad semantics)
#define WB     2176            // buffer width in floats
#define W4     (WB/4)
#define HB     2080            // buffer height
#define PLANE  (HB*WB)
#define NSTRIP 19              // 19 strips * 28 float4 = 532 >= 516 domain float4 cols
#define SROWS  36              // even; 5 x 58 x 3 = 870 blocks <= 148 SM x 6 = 888 (one wave)
#define NRB    58              // 57*36 = 2052; last block rows 2052..2061 = 10 (even)
#define NITER  10

// ping-pong state, planar per channel, zero-initialized at module load;
// guard bands are NEVER written -> stay zero across all graph replays
__device__ float g_bufA[3*PLANE];
__device__ float g_bufB[3*PLANE];

// ---------------- pad: img (HWC, edge-pad 7) -> bufA domain region only ----------------
__global__ void pad_kernel(const float* __restrict__ img) {
    int bc = GUARD + blockIdx.x*blockDim.x + threadIdx.x;   // domain col in buffer coords
    int br = GUARD + blockIdx.y;                            // domain row in buffer coords
    int ch = blockIdx.z;
    if (bc >= GUARD+DOM) return;
    int u = br - (GUARD+RAD);
    int w = bc - (GUARD+RAD);
    u = min(max(u,0), IMG-1);
    w = min(max(w,0), IMG-1);
    g_bufA[ch*PLANE + br*WB + bc] = img[(u*IMG + w)*3 + ch];
}

// ---------------- packed f32x2 helpers (Blackwell) ----------------
typedef unsigned long long u64;
#define NEG1P 0xBF800000BF800000ULL     // {-1.0f, -1.0f}

__device__ __forceinline__ u64 pk2(float lo, float hi){
    u64 r; asm("mov.b64 %0, {%1, %2};" : "=l"(r) : "f"(lo), "f"(hi)); return r;
}
__device__ __forceinline__ void up2(u64 v, float& lo, float& hi){
    asm("mov.b64 {%0, %1}, %2;" : "=f"(lo), "=f"(hi) : "l"(v));
}
__device__ __forceinline__ u64 fadd2(u64 a, u64 b){
    u64 r; asm("add.rn.f32x2 %0, %1, %2;" : "=l"(r) : "l"(a), "l"(b)); return r;
}
__device__ __forceinline__ u64 fmul2(u64 a, u64 b){
    u64 r; asm("mul.rn.f32x2 %0, %1, %2;" : "=l"(r) : "l"(a), "l"(b)); return r;
}
__device__ __forceinline__ u64 ffma2(u64 a, u64 b, u64 c){
    u64 r; asm("fma.rn.f32x2 %0, %1, %2, %3;" : "=l"(r) : "l"(a), "l"(b), "l"(c)); return r;
}
__device__ __forceinline__ u64 fsub2(u64 a, u64 b){     // a - b (exact: fma(b,-1,a))
    return ffma2(b, NEG1P, a);
}

struct P4 { u64 ab, cd; };               // packed float4: {x,y},{z,w}
__device__ __forceinline__ P4 p4add(P4 a, P4 b){ P4 r; r.ab=fadd2(a.ab,b.ab); r.cd=fadd2(a.cd,b.cd); return r; }
__device__ __forceinline__ P4 p4sub(P4 a, P4 b){ P4 r; r.ab=fsub2(a.ab,b.ab); r.cd=fsub2(a.cd,b.cd); return r; }
__device__ __forceinline__ P4 ldp4(const float4* p){
    float4 v = __ldg(p);
    P4 r; r.ab = pk2(v.x, v.y); r.cd = pk2(v.z, v.w); return r;
}

// rotate-left-1 key: (abs_bits << 1) | sign  — unsigned order == |value| order,
// bijective with the float bits (recover via rotate-right-1)
__device__ __forceinline__ unsigned keyof(float d) {
    unsigned b = __float_as_uint(d);
    return __funnelshift_l(b, b, 1);
}

// 8-wide left/right window sums for this lane's 4 columns, all-shuffle exchange.
// Lane t owns chunk cols [4t, 4t+4). With w[k] = value at col 4(t-2)+k:
//   l[j] = sum w[j+1 .. j+8], r[j] = sum w[j+8 .. j+15]
__device__ __forceinline__ void awin(float ax, float ay, float az, float aw,
                                     float* l, float* r) {
    const unsigned FULL = 0xffffffffu;
    float P2 = ax + ay;
    float P3 = P2 + az;
    float S2 = az + aw;
    float S3 = ay + S2;
    float C  = P3 + aw;
    float uS1 = __shfl_up_sync  (FULL, aw, 2);
    float uS2 = __shfl_up_sync  (FULL, S2, 2);
    float uS3 = __shfl_up_sync  (FULL, S3, 2);
    float uC  = __shfl_up_sync  (FULL, C,  1);
    float dC  = __shfl_down_sync(FULL, C,  1);
    float dP1 = __shfl_down_sync(FULL, ax, 2);
    float dP2 = __shfl_down_sync(FULL, P2, 2);
    float dP3 = __shfl_down_sync(FULL, P3, 2);
    l[0] = uS3 + uC + ax;
    l[1] = uS2 + uC + P2;
    l[2] = uS1 + uC + P3;
    l[3] = uC  + C;
    r[0] = C   + dC;
    r[1] = S3  + dC + dP1;
    r[2] = S2  + dC + dP2;
    r[3] = aw  + dC + dP3;
}

// full side-window pass for one row; unconditional compute, predicated store
__device__ __forceinline__ void do_row(P4 sT, P4 sB, P4 xc, int i,
                                       float4* __restrict__ dst4,
                                       float*  __restrict__ dstp,
                                       int c4, bool isOut, bool full4) {
    const u64 S8p  = pk2(1.0f/64.0f,  1.0f/64.0f);
    const u64 S15p = pk2(1.0f/120.0f, 1.0f/120.0f);

    // full 15-row vertical sum (packed)
    u64 sVab = fsub2(fadd2(sT.ab, sB.ab), xc.ab);
    u64 sVcd = fsub2(fadd2(sT.cd, sB.cd), xc.cd);

    float t0,t1,t2,t3, b0,b1,b2,b3, v0,v1,v2,v3;
    up2(sT.ab, t0,t1); up2(sT.cd, t2,t3);
    up2(sB.ab, b0,b1); up2(sB.cd, b2,b3);
    up2(sVab,  v0,v1); up2(sVcd,  v2,v3);

    float lT[4], rT[4], lB[4], rB[4], lV[4], rV[4];
    awin(t0,t1,t2,t3, lT, rT);
    awin(b0,b1,b2,b3, lB, rB);
    awin(v0,v1,v2,v3, lV, rV);

    float res[4];
    #pragma unroll
    for (int p = 0; p < 2; ++p) {       // pixel pairs (j0,j1) and (j2,j3)
        u64 xp  = p ? xc.cd : xc.ab;
        u64 fTp = p ? sT.cd : sT.ab;
        u64 fBp = p ? sB.cd : sB.ab;
        u64 lTp = pk2(lT[2*p], lT[2*p+1]);
        u64 rTp = pk2(rT[2*p], rT[2*p+1]);
        u64 lBp = pk2(lB[2*p], lB[2*p+1]);
        u64 rBp = pk2(rB[2*p], rB[2*p+1]);
        u64 lVp = pk2(lV[2*p], lV[2*p+1]);
        u64 rVp = pk2(rV[2*p], rV[2*p+1]);

        u64 nx  = fmul2(xp, NEG1P);                 // exact -x pair
        u64 fAp = fsub2(fadd2(lTp, rTp), fTp);      // full-15 horiz of top sums (N)
        u64 fSp = fsub2(fadd2(lBp, rBp), fBp);      // full-15 horiz of bottom sums (S)

        // channel order matches reference stack: NW NE SW SE N S W E
        u64 d0 = ffma2(lTp, S8p,  nx);
        u64 d1 = ffma2(rTp, S8p,  nx);
        u64 d2 = ffma2(lBp, S8p,  nx);
        u64 d3 = ffma2(rBp, S8p,  nx);
        u64 d4 = ffma2(fAp, S15p, nx);
        u64 d5 = ffma2(fSp, S15p, nx);
        u64 d6 = ffma2(lVp, S15p, nx);
        u64 d7 = ffma2(rVp, S15p, nx);

        float e0,f0_, e1,f1_, e2,f2_, e3,f3_, e4,f4_, e5,f5_, e6,f6_, e7,f7_;
        up2(d0, e0,f0_); up2(d1, e1,f1_); up2(d2, e2,f2_); up2(d3, e3,f3_);
        up2(d4, e4,f4_); up2(d5, e5,f5_); up2(d6, e6,f6_); up2(d7, e7,f7_);
        float xlo, xhi; up2(xp, xlo, xhi);

        {   // element 2p : min-|d| via rotated-bits unsigned keys, depth-3 IMNMX tree
            unsigned m = min(min(min(keyof(e0),keyof(e1)), min(keyof(e2),keyof(e3))),
                             min(min(keyof(e4),keyof(e5)), min(keyof(e6),keyof(e7))));
            res[2*p] = xlo + __uint_as_float(__funnelshift_r(m, m, 1));
        }
        {   // element 2p+1
            unsigned m = min(min(min(keyof(f0_),keyof(f1_)), min(keyof(f2_),keyof(f3_))),
                             min(min(keyof(f4_),keyof(f5_)), min(keyof(f6_),keyof(f7_))));
            res[2*p+1] = xhi + __uint_as_float(__funnelshift_r(m, m, 1));
        }
    }

    if (isOut & full4) {
        dst4[(i+8)*W4 + c4] = make_float4(res[0], res[1], res[2], res[3]);
    } else if (isOut) {
        // c4 == 517: only buffer cols 2068, 2069 are inside the domain
        dstp[(i+8)*WB + 4*c4 + 0] = res[0];
        dstp[(i+8)*WB + 4*c4 + 1] = res[1];
    }
}

// ---------------- one full side-window iteration, 2 rows per loop ----------------
__global__ __launch_bounds__(128,6) void iter_kernel(int sel) {
    const int t = threadIdx.x & 31;
    const int w = threadIdx.x >> 5;
    const int strip = blockIdx.x*4 + w;
    if (strip >= NSTRIP) return;      // warps fully independent, no block sync anywhere
    const int ch = blockIdx.z;
    const float* __restrict__ srcp = (sel ? g_bufB : g_bufA) + ch*PLANE;
    float*       __restrict__ dstp = (sel ? g_bufA : g_bufB) + ch*PLANE;
    const float4* __restrict__ src4 = reinterpret_cast<const float4*>(srcp);
    float4*       __restrict__ dst4 = reinterpret_cast<float4*>(dstp);

    const int c4 = strip*28 + t;      // buffer float4 column (max 535 < 544)
    const int r0 = blockIdx.y*SROWS;
    const int rend = min(r0 + SROWS, DOM);   // rend - r0 always even (36 or 10)

    // warm-up: sT = buffer rows r0+1..r0+8, sB = rows r0+8..r0+15, xc = row r0+8
    P4 sT; sT.ab = 0; sT.cd = 0;
    P4 sB; sB.ab = 0; sB.cd = 0;
    P4 xc; xc.ab = 0; xc.cd = 0;
    #pragma unroll
    for (int k = 1; k <= 15; ++k) {
        P4 v = ldp4(&src4[(r0+k)*W4 + c4]);
        if (k <= 8) sT = p4add(sT, v);
        if (k >= 8) sB = p4add(sB, v);
        if (k == 8) xc = v;
    }

    const bool isOut = (t >= 2) && (t < 30) && (c4 <= 517);
    const bool full4 = (c4 <= 516);

    for (int i = r0; i < rend; i += 2) {
        // all six slide inputs for the row pair, issued up front
        P4 rA = ldp4(&src4[(i+9)*W4  + c4]);   // aT for row i; center of row i+1
        P4 rB = ldp4(&src4[(i+1)*W4  + c4]);   // bT for row i
        P4 rC = ldp4(&src4[(i+16)*W4 + c4]);   // aB for row i
        P4 rD = ldp4(&src4[(i+10)*W4 + c4]);   // aT for row i+1; next center
        P4 rE = ldp4(&src4[(i+2)*W4  + c4]);   // bT for row i+1
        P4 rF = ldp4(&src4[(i+17)*W4 + c4]);   // aB for row i+1

        do_row(sT, sB, xc, i, dst4, dstp, c4, isOut, full4);

        P4 sT1 = p4sub(p4add(sT, rA), rB);
        P4 sB1 = p4sub(p4add(sB, rC), xc);

        do_row(sT1, sB1, rA, i+1, dst4, dstp, c4, isOut, full4);

        sT = p4sub(p4add(sT1, rD), rE);
        sB = p4sub(p4add(sB1, rF), rA);
        xc = rD;
    }
}

// ---------------- crop: bufA planar -> d_out HWC ----------------
__global__ void crop_kernel(float* __restrict__ out) {
    int x = blockIdx.x*blockDim.x + threadIdx.x;
    int y = blockIdx.y;
    if (x >= IMG) return;
    int br = y + RAD + GUARD;
    int bc = x + RAD + GUARD;
    float* o = out + (size_t)(y*IMG + x)*3;
    o[0] = g_bufA[0*PLANE + br*WB + bc];
    o[1] = g_bufA[1*PLANE + br*WB + bc];
    o[2] = g_bufA[2*PLANE + br*WB + bc];
}

extern "C" void kernel_launch(void* const* d_in, const int* in_sizes, int n_in,
                              void* d_out, int out_size) {
    (void)in_sizes; (void)n_in; (void)out_size;
    const float* img = (const float*)d_in[0];   // d_in[1], d_in[2] are fixed constant kernels
    float* out = (float*)d_out;

    pad_kernel<<<dim3((DOM + 255)/256, DOM, 3), 256>>>(img);

    for (int it = 0; it < NITER; ++it)
        iter_kernel<<<dim3(5, NRB, 3), 128>>>(it & 1);
    // it=0: A->B, it=1: B->A, ... it=9: B->A  => final state in g_bufA

    crop_kernel<<<dim3((IMG + 255)/256, IMG), 256>>>(out);
}

// round 11
// speedup vs baseline: 1.2037x; 1.0231x over previous
#include <cuda_runtime.h>

// ---------------- geometry ----------------
#define RAD    7
#define IMG    2048
#define DOM    2062            // IMG + 2*RAD : iterated domain
#define GUARD  8               // zero guard band around DOM (zero-pad semantics)
#define WB     2176            // buffer width in floats
#define W4     (WB/4)
#define HB     2080            // buffer height
#define PLANE  (HB*WB)
#define NSTRIP 19              // 19 strips * 28 float4 = 532 >= 516 domain float4 cols
#define SROWS  30              // even; 5 x 69 x 3 = 1035 blocks <= 148 SM x 7 = 1036 (one wave)
#define NRB    69              // 68*30 = 2040; last block rows 2040..2061 = 22 (even)
#define NITER  10

// ping-pong state, planar per channel, zero-initialized at module load;
// guard bands are NEVER written -> stay zero across all graph replays
__device__ float g_bufA[3*PLANE];
__device__ float g_bufB[3*PLANE];

// ---------------- pad: img (HWC, edge-pad 7) -> bufA domain region only ----------------
__global__ void pad_kernel(const float* __restrict__ img) {
    int bc = GUARD + blockIdx.x*blockDim.x + threadIdx.x;   // domain col in buffer coords
    int br = GUARD + blockIdx.y;                            // domain row in buffer coords
    int ch = blockIdx.z;
    if (bc >= GUARD+DOM) return;
    int u = br - (GUARD+RAD);
    int w = bc - (GUARD+RAD);
    u = min(max(u,0), IMG-1);
    w = min(max(w,0), IMG-1);
    g_bufA[ch*PLANE + br*WB + bc] = img[(u*IMG + w)*3 + ch];
}

// ---------------- packed f32x2 helpers (Blackwell) ----------------
typedef unsigned long long u64;
#define NEG1P 0xBF800000BF800000ULL     // {-1.0f, -1.0f}

__device__ __forceinline__ u64 pk2(float lo, float hi){
    u64 r; asm("mov.b64 %0, {%1, %2};" : "=l"(r) : "f"(lo), "f"(hi)); return r;
}
__device__ __forceinline__ void up2(u64 v, float& lo, float& hi){
    asm("mov.b64 {%0, %1}, %2;" : "=f"(lo), "=f"(hi) : "l"(v));
}
__device__ __forceinline__ u64 fadd2(u64 a, u64 b){
    u64 r; asm("add.rn.f32x2 %0, %1, %2;" : "=l"(r) : "l"(a), "l"(b)); return r;
}
__device__ __forceinline__ u64 fmul2(u64 a, u64 b){
    u64 r; asm("mul.rn.f32x2 %0, %1, %2;" : "=l"(r) : "l"(a), "l"(b)); return r;
}
__device__ __forceinline__ u64 ffma2(u64 a, u64 b, u64 c){
    u64 r; asm("fma.rn.f32x2 %0, %1, %2, %3;" : "=l"(r) : "l"(a), "l"(b), "l"(c)); return r;
}
__device__ __forceinline__ u64 fsub2(u64 a, u64 b){     // a - b (exact: fma(b,-1,a))
    return ffma2(b, NEG1P, a);
}

struct P4 { u64 ab, cd; };               // packed float4: {x,y},{z,w}
__device__ __forceinline__ P4 p4add(P4 a, P4 b){ P4 r; r.ab=fadd2(a.ab,b.ab); r.cd=fadd2(a.cd,b.cd); return r; }
__device__ __forceinline__ P4 p4sub(P4 a, P4 b){ P4 r; r.ab=fsub2(a.ab,b.ab); r.cd=fsub2(a.cd,b.cd); return r; }
__device__ __forceinline__ P4 ldp4(const float4* p){
    float4 v = __ldg(p);
    P4 r; r.ab = pk2(v.x, v.y); r.cd = pk2(v.z, v.w); return r;
}

// rotate-left-1 key: (abs_bits << 1) | sign  — unsigned order == |value| order,
// bijective with the float bits (recover via rotate-right-1)
__device__ __forceinline__ unsigned keyof(float d) {
    unsigned b = __float_as_uint(d);
    return __funnelshift_l(b, b, 1);
}

// 8-wide left/right window sums for this lane's 4 columns, all-shuffle exchange.
// Lane t owns chunk cols [4t, 4t+4). With w[k] = value at col 4(t-2)+k:
//   l[j] = sum w[j+1 .. j+8], r[j] = sum w[j+8 .. j+15]
__device__ __forceinline__ void awin(float ax, float ay, float az, float aw,
                                     float* l, float* r) {
    const unsigned FULL = 0xffffffffu;
    float P2 = ax + ay;
    float P3 = P2 + az;
    float S2 = az + aw;
    float S3 = ay + S2;
    float C  = P3 + aw;
    float uS1 = __shfl_up_sync  (FULL, aw, 2);
    float uS2 = __shfl_up_sync  (FULL, S2, 2);
    float uS3 = __shfl_up_sync  (FULL, S3, 2);
    float uC  = __shfl_up_sync  (FULL, C,  1);
    float dC  = __shfl_down_sync(FULL, C,  1);
    float dP1 = __shfl_down_sync(FULL, ax, 2);
    float dP2 = __shfl_down_sync(FULL, P2, 2);
    float dP3 = __shfl_down_sync(FULL, P3, 2);
    l[0] = uS3 + uC + ax;
    l[1] = uS2 + uC + P2;
    l[2] = uS1 + uC + P3;
    l[3] = uC  + C;
    r[0] = C   + dC;
    r[1] = S3  + dC + dP1;
    r[2] = S2  + dC + dP2;
    r[3] = aw  + dC + dP3;
}

// full side-window pass for one row; unconditional compute, predicated store.
// FINAL=false: store float4 into dst buffer.  FINAL=true: scatter HWC into outp.
template<bool FINAL>
__device__ __forceinline__ void do_row(P4 sT, P4 sB, P4 xc, int i,
                                       float4* __restrict__ dst4,
                                       float*  __restrict__ dstp,
                                       float*  __restrict__ outp, int ch,
                                       int c4, bool isOut, bool full4) {
    const u64 S8p  = pk2(1.0f/64.0f,  1.0f/64.0f);
    const u64 S15p = pk2(1.0f/120.0f, 1.0f/120.0f);

    // full 15-row vertical sum (packed)
    u64 sVab = fsub2(fadd2(sT.ab, sB.ab), xc.ab);
    u64 sVcd = fsub2(fadd2(sT.cd, sB.cd), xc.cd);

    float t0,t1,t2,t3, b0,b1,b2,b3, v0,v1,v2,v3;
    up2(sT.ab, t0,t1); up2(sT.cd, t2,t3);
    up2(sB.ab, b0,b1); up2(sB.cd, b2,b3);
    up2(sVab,  v0,v1); up2(sVcd,  v2,v3);

    float lT[4], rT[4], lB[4], rB[4], lV[4], rV[4];
    awin(t0,t1,t2,t3, lT, rT);
    awin(b0,b1,b2,b3, lB, rB);
    awin(v0,v1,v2,v3, lV, rV);

    float res[4];
    #pragma unroll
    for (int p = 0; p < 2; ++p) {       // pixel pairs (j0,j1) and (j2,j3)
        u64 xp  = p ? xc.cd : xc.ab;
        u64 fTp = p ? sT.cd : sT.ab;
        u64 fBp = p ? sB.cd : sB.ab;
        u64 lTp = pk2(lT[2*p], lT[2*p+1]);
        u64 rTp = pk2(rT[2*p], rT[2*p+1]);
        u64 lBp = pk2(lB[2*p], lB[2*p+1]);
        u64 rBp = pk2(rB[2*p], rB[2*p+1]);
        u64 lVp = pk2(lV[2*p], lV[2*p+1]);
        u64 rVp = pk2(rV[2*p], rV[2*p+1]);

        u64 nx  = fmul2(xp, NEG1P);                 // exact -x pair
        u64 fAp = fsub2(fadd2(lTp, rTp), fTp);      // full-15 horiz of top sums (N)
        u64 fSp = fsub2(fadd2(lBp, rBp), fBp);      // full-15 horiz of bottom sums (S)

        // channel order matches reference stack: NW NE SW SE N S W E
        u64 d0 = ffma2(lTp, S8p,  nx);
        u64 d1 = ffma2(rTp, S8p,  nx);
        u64 d2 = ffma2(lBp, S8p,  nx);
        u64 d3 = ffma2(rBp, S8p,  nx);
        u64 d4 = ffma2(fAp, S15p, nx);
        u64 d5 = ffma2(fSp, S15p, nx);
        u64 d6 = ffma2(lVp, S15p, nx);
        u64 d7 = ffma2(rVp, S15p, nx);

        float e0,f0_, e1,f1_, e2,f2_, e3,f3_, e4,f4_, e5,f5_, e6,f6_, e7,f7_;
        up2(d0, e0,f0_); up2(d1, e1,f1_); up2(d2, e2,f2_); up2(d3, e3,f3_);
        up2(d4, e4,f4_); up2(d5, e5,f5_); up2(d6, e6,f6_); up2(d7, e7,f7_);
        float xlo, xhi; up2(xp, xlo, xhi);

        {   // element 2p : min-|d| via rotated-bits unsigned keys, depth-3 IMNMX tree
            unsigned m = min(min(min(keyof(e0),keyof(e1)), min(keyof(e2),keyof(e3))),
                             min(min(keyof(e4),keyof(e5)), min(keyof(e6),keyof(e7))));
            res[2*p] = xlo + __uint_as_float(__funnelshift_r(m, m, 1));
        }
        {   // element 2p+1
            unsigned m = min(min(min(keyof(f0_),keyof(f1_)), min(keyof(f2_),keyof(f3_))),
                             min(min(keyof(f4_),keyof(f5_)), min(keyof(f6_),keyof(f7_))));
            res[2*p+1] = xhi + __uint_as_float(__funnelshift_r(m, m, 1));
        }
    }

    if (FINAL) {
        // write crop region directly to d_out (HWC); no buffer write needed
        int y = i - RAD;
        if (isOut && (unsigned)y < (unsigned)IMG) {
            #pragma unroll
            for (int j = 0; j < 4; ++j) {
                int x = 4*c4 + j - (GUARD+RAD);
                if ((unsigned)x < (unsigned)IMG)
                    outp[((size_t)y*IMG + x)*3 + ch] = res[j];
            }
        }
    } else {
        if (isOut & full4) {
            dst4[(i+8)*W4 + c4] = make_float4(res[0], res[1], res[2], res[3]);
        } else if (isOut) {
            // c4 == 517: only buffer cols 2068, 2069 are inside the domain
            dstp[(i+8)*WB + 4*c4 + 0] = res[0];
            dstp[(i+8)*WB + 4*c4 + 1] = res[1];
        }
    }
}

// ---------------- one full side-window iteration, 2 rows per loop ----------------
template<bool FINAL>
__global__ __launch_bounds__(128,7) void iter_kernel_t(int sel, float* __restrict__ outp) {
    const int t = threadIdx.x & 31;
    const int w = threadIdx.x >> 5;
    const int strip = blockIdx.x*4 + w;
    if (strip >= NSTRIP) return;      // warps fully independent, no block sync anywhere
    const int ch = blockIdx.z;
    const float* __restrict__ srcp = (sel ? g_bufB : g_bufA) + ch*PLANE;
    float*       __restrict__ dstp = (sel ? g_bufA : g_bufB) + ch*PLANE;
    const float4* __restrict__ src4 = reinterpret_cast<const float4*>(srcp);
    float4*       __restrict__ dst4 = reinterpret_cast<float4*>(dstp);

    const int c4 = strip*28 + t;      // buffer float4 column (max 535 < 544)
    const int r0 = blockIdx.y*SROWS;
    const int rend = min(r0 + SROWS, DOM);   // rend - r0 always even (30 or 22)

    // warm-up: sT = buffer rows r0+1..r0+8, sB = rows r0+8..r0+15, xc = row r0+8
    P4 sT; sT.ab = 0; sT.cd = 0;
    P4 sB; sB.ab = 0; sB.cd = 0;
    P4 xc; xc.ab = 0; xc.cd = 0;
    #pragma unroll
    for (int k = 1; k <= 15; ++k) {
        P4 v = ldp4(&src4[(r0+k)*W4 + c4]);
        if (k <= 8) sT = p4add(sT, v);
        if (k >= 8) sB = p4add(sB, v);
        if (k == 8) xc = v;
    }

    const bool isOut = (t >= 2) && (t < 30) && (c4 <= 517);
    const bool full4 = (c4 <= 516);

    for (int i = r0; i < rend; i += 2) {
        // all six slide inputs for the row pair, issued up front
        P4 rA = ldp4(&src4[(i+9)*W4  + c4]);   // aT for row i; center of row i+1
        P4 rB = ldp4(&src4[(i+1)*W4  + c4]);   // bT for row i
        P4 rC = ldp4(&src4[(i+16)*W4 + c4]);   // aB for row i
        P4 rD = ldp4(&src4[(i+10)*W4 + c4]);   // aT for row i+1; next center
        P4 rE = ldp4(&src4[(i+2)*W4  + c4]);   // bT for row i+1
        P4 rF = ldp4(&src4[(i+17)*W4 + c4]);   // aB for row i+1

        do_row<FINAL>(sT, sB, xc, i, dst4, dstp, outp, ch, c4, isOut, full4);

        P4 sT1 = p4sub(p4add(sT, rA), rB);
        P4 sB1 = p4sub(p4add(sB, rC), xc);

        do_row<FINAL>(sT1, sB1, rA, i+1, dst4, dstp, outp, ch, c4, isOut, full4);

        sT = p4sub(p4add(sT1, rD), rE);
        sB = p4sub(p4add(sB1, rF), rA);
        xc = rD;
    }
}

extern "C" void kernel_launch(void* const* d_in, const int* in_sizes, int n_in,
                              void* d_out, int out_size) {
    (void)in_sizes; (void)n_in; (void)out_size;
    const float* img = (const float*)d_in[0];   // d_in[1], d_in[2] are fixed constant kernels
    float* out = (float*)d_out;

    pad_kernel<<<dim3((DOM + 255)/256, DOM, 3), 256>>>(img);

    // iterations 0..8 ping-pong between buffers (it0: A->B, it8: A->B)
    for (int it = 0; it < NITER-1; ++it)
        iter_kernel_t<false><<<dim3(5, NRB, 3), 128>>>(it & 1, nullptr);

    // final iteration reads bufB, writes the cropped result directly to d_out (HWC)
    iter_kernel_t<true><<<dim3(5, NRB, 3), 128>>>(1, out);
}